// round 13
// baseline (speedup 1.0000x reference)
#include <cuda_runtime.h>
#include <cuda_bf16.h>
#include <cstdint>

// Problem constants
#define U_ROWS 50000
#define N_ITEMS 4000
#define BATCH 256
#define MAXK 64
#define CAND 32                 // candidates per row, rescored exactly
#define NBLK 391                // GEMM CTAs = ceil(50000/128)
#define PK 8                    // per-(b, CTA) partial top-k

// GEMM config: CTA tile 128(M) x 256(N), BK=32, 3-stage ring
#define BK 32
#define KITERS (N_ITEMS / BK)   // 125
#define NTHREADS 512            // 16 warps: 2(M) x 8(N), warp tile 64x32

#define STAGE_BYTES 24576       // A bf16 128x64B (8K) + B bf16 256x64B (16K)
// Csm[128][257] floats = 131584 bytes reuses the stage region post-mainloop
#define OFF_INVNA 131584
#define OFF_INVNU (OFF_INVNA + 512)
#define OFF_PKBUF (OFF_INVNU + 1024)        // 512 threads x PK x 8B = 32768
#define SMEM_TOTAL (OFF_PKBUF + 512 * PK * 8 + 64)

// ---------------- scratch (static device memory) ---------------------------
__device__ __align__(16) float g_users[(size_t)BATCH * N_ITEMS];           // 4 MB fp32
__device__ __align__(16) __nv_bfloat16 g_users_bf[(size_t)BATCH * N_ITEMS];// 2 MB
__device__ __align__(16) unsigned long long g_pk[(size_t)BATCH * NBLK * PK]; // 6.4 MB
__device__ float g_inv_na[U_ROWS];
__device__ float g_inv_nu[BATCH];
__device__ int   g_cand_idx[BATCH * CAND];
__device__ float g_cand_sim[BATCH * CAND];
__device__ float g_wgt[BATCH * MAXK];
__device__ int   g_nid[BATCH * MAXK];
__device__ int   g_k;

// ---------------- helpers ---------------------------------------------------
__device__ __forceinline__ uint32_t smem_u32(const void* p) {
    uint32_t a;
    asm("{ .reg .u64 t; cvta.to.shared.u64 t, %1; cvt.u32.u64 %0, t; }" : "=r"(a) : "l"(p));
    return a;
}
#define CP_ASYNC16(dst, src) \
    asm volatile("cp.async.cg.shared.global [%0], [%1], 16;" :: "r"(dst), "l"(src))
#define CP_COMMIT() asm volatile("cp.async.commit_group;" ::: "memory")
#define CP_WAIT(n)  asm volatile("cp.async.wait_group %0;" :: "n"(n) : "memory")

__device__ __forceinline__ float neg_inf() { return __int_as_float(0xFF800000); }
__device__ __forceinline__ unsigned bf16u(float x) {
    return (unsigned)__bfloat16_as_ushort(__float2bfloat16_rn(x));
}
__device__ __forceinline__ uint32_t pack_bf2(float a, float b) {
    uint32_t r;
    asm("cvt.rn.bf16x2.f32 %0, %2, %1;" : "=r"(r) : "f"(a), "f"(b));
    return r;
}
// swizzled chunk byte offset within a 64B-row tile
__device__ __forceinline__ uint32_t swz64(int row, int c) {
    return (uint32_t)(row * 64 + 16 * (c ^ ((row >> 1) & 3)));
}
// order-preserving composite key: (value desc, index asc); key > 0 for v >= 0
__device__ __forceinline__ unsigned long long okey(float v, int idx) {
    unsigned kb = __float_as_uint(v);
    kb ^= (kb >> 31) ? 0xFFFFFFFFu : 0x80000000u;
    return ((unsigned long long)kb << 32) |
           (unsigned long long)(0xFFFFFFFFu - (unsigned)idx);
}
__device__ __forceinline__ int okey_idx(unsigned long long k) {
    return (int)(0xFFFFFFFFu - (unsigned)(k & 0xFFFFFFFFull));
}

// ---------------- kernel 1: gather users + norms + mode/k detection ---------
__global__ void gather_users_kernel(const float* __restrict__ F, const void* ids,
                                    const int* kptr, int has_k) {
    const int b = blockIdx.x;
    const int tid = threadIdx.x;

    __shared__ int s_is64;
    if (tid == 0) {
        const unsigned* w = (const unsigned*)ids;
        bool is64 = true;
        for (int i = 0; i < 16; i++)
            if (w[2 * i + 1] != 0u) { is64 = false; break; }
        s_is64 = is64 ? 1 : 0;
        if (b == 0) {
            int kk = 10;
            if (has_k) {
                int vi = kptr[0];
                if (vi >= 1 && vi <= MAXK) kk = vi;
                else {
                    float vf = __int_as_float(vi);
                    if (vf >= 1.f && vf <= (float)MAXK) kk = (int)vf;
                }
            }
            g_k = kk;
        }
    }
    __syncthreads();

    long long uid;
    if (s_is64) uid = ((const long long*)ids)[b];
    else        uid = (long long)((const int*)ids)[b];
    const float4* src = (const float4*)(F + (size_t)uid * N_ITEMS);
    float4* dstf = (float4*)(g_users + (size_t)b * N_ITEMS);
    uint2* dstb = (uint2*)(g_users_bf + (size_t)b * N_ITEMS);
    float s = 0.f;
    for (int v = tid; v < N_ITEMS / 4; v += 256) {
        float4 x = src[v];
        dstf[v] = x;
        uint2 o;
        o.x = bf16u(x.x) | (bf16u(x.y) << 16);
        o.y = bf16u(x.z) | (bf16u(x.w) << 16);
        dstb[v] = o;
        s += x.x * x.x + x.y * x.y + x.z * x.z + x.w * x.w;
    }
    for (int off = 16; off > 0; off >>= 1)
        s += __shfl_down_sync(0xFFFFFFFFu, s, off);
    __shared__ float ws[8];
    if ((tid & 31) == 0) ws[tid >> 5] = s;
    __syncthreads();
    if (tid == 0) {
        float t = 0.f;
        for (int i = 0; i < 8; i++) t += ws[i];
        g_inv_nu[b] = 1.0f / fmaxf(t, 1e-8f);
    }
}

// ---------------- kernel 2: bf16 mma GEMM + fused per-CTA top-PK ------------
__global__ __launch_bounds__(NTHREADS, 1)
void gemm_sim_kernel(const float* __restrict__ F) {
    extern __shared__ __align__(1024) char smem[];
    const uint32_t sbase = smem_u32(smem);
    const int tid = threadIdx.x;
    const int lane = tid & 31;
    const int wid = tid >> 5;
    const int m0 = blockIdx.x * 128;
    const int mw = wid & 1;       // warp M index
    const int nw = wid >> 1;      // warp N index (0..7), warp tile 64x32

    float* invna_s = (float*)(smem + OFF_INVNA);
    float* invnu_s = (float*)(smem + OFF_INVNU);
    if (tid < 256) invnu_s[tid] = g_inv_nu[tid];

    // ---- A producer (fp32 LDG -> cvt -> STS): thread owns (row, 16B chunk) ----
    const int arow = tid >> 2;           // 0..127
    const int ach = tid & 3;             // bf16 16B chunk == fp32 32B chunk
    int gm = m0 + arow; if (gm > U_ROWS - 1) gm = U_ROWS - 1;
    const char* asrc = (const char*)F + (size_t)gm * (N_ITEMS * 4) + ach * 32;
    const uint32_t asts = swz64(arow, ach);

    // ---- B producer (cp.async from bf16 users): rows arow, arow+128 ----
    const char* bsrc0 = (const char*)g_users_bf + (size_t)arow * (N_ITEMS * 2) + ach * 16;
    const char* bsrc1 = bsrc0 + (size_t)128 * (N_ITEMS * 2);
    const uint32_t bst0 = 8192 + swz64(arow, ach);
    const uint32_t bst1 = 8192 + swz64(arow + 128, ach);

    // ---- A fragment (ldmatrix) per-lane constants ----
    const int ahalf = lane >> 4;
    uint32_t a_base[4];
    int a_sw[4];
#pragma unroll
    for (int f = 0; f < 4; f++) {
        int r = mw * 64 + f * 16 + (lane & 15);
        a_base[f] = (uint32_t)(r * 64);
        a_sw[f] = (r >> 1) & 3;
    }
    // ---- B fragment (ldmatrix x4 over 16n x 16k) per-lane constants ----
    const int grp = lane >> 3;
    const int cbit = grp & 1;
    uint32_t b_base[2];
    int b_sw[2];
#pragma unroll
    for (int gp = 0; gp < 2; gp++) {
        int n = nw * 32 + gp * 16 + ((grp & 2) << 2) + (lane & 7);
        b_base[gp] = (uint32_t)(8192 + n * 64);
        b_sw[gp] = (n >> 1) & 3;
    }

    float c[4][4][4];
#pragma unroll
    for (int f = 0; f < 4; f++)
#pragma unroll
        for (int g = 0; g < 4; g++)
#pragma unroll
            for (int i = 0; i < 4; i++) c[f][g][i] = 0.f;

    float ns = 0.f;
    float4 av0, av1;

    auto ldgA = [&](int kt) {
        const char* p = asrc + (size_t)kt * (BK * 4);
        av0 = *(const float4*)p;
        av1 = *(const float4*)(p + 16);
    };
    auto stsA = [&](uint32_t stagebase) {
        ns += av0.x * av0.x + av0.y * av0.y + av0.z * av0.z + av0.w * av0.w;
        ns += av1.x * av1.x + av1.y * av1.y + av1.z * av1.z + av1.w * av1.w;
        uint32_t p0 = pack_bf2(av0.x, av0.y);
        uint32_t p1 = pack_bf2(av0.z, av0.w);
        uint32_t p2 = pack_bf2(av1.x, av1.y);
        uint32_t p3 = pack_bf2(av1.z, av1.w);
        asm volatile("st.shared.v4.b32 [%0], {%1,%2,%3,%4};"
                     :: "r"(stagebase + asts), "r"(p0), "r"(p1), "r"(p2), "r"(p3)
                     : "memory");
    };
    auto issueB = [&](int kt) {
        uint32_t stb = sbase + (kt % 3) * STAGE_BYTES;
        CP_ASYNC16(stb + bst0, bsrc0 + (size_t)kt * (BK * 2));
        CP_ASYNC16(stb + bst1, bsrc1 + (size_t)kt * (BK * 2));
    };

    // ---- prologue ----
    issueB(0); CP_COMMIT();
    issueB(1); CP_COMMIT();
    ldgA(0);
    stsA(sbase);
    ldgA(1);

    // ---- mainloop ----
    for (int kt = 0; kt < KITERS; ++kt) {
        CP_WAIT(1);
        __syncthreads();
        if (kt + 2 < KITERS) issueB(kt + 2);
        CP_COMMIT();
        if (kt + 1 < KITERS) stsA(sbase + ((kt + 1) % 3) * STAGE_BYTES);
        if (kt + 2 < KITERS) ldgA(kt + 2);

        const uint32_t stb = sbase + (kt % 3) * STAGE_BYTES;
#pragma unroll
        for (int s = 0; s < 2; ++s) {
            uint32_t af[4][4];
#pragma unroll
            for (int f = 0; f < 4; ++f) {
                uint32_t addr = stb + a_base[f] +
                                (uint32_t)(16 * ((2 * s + ahalf) ^ a_sw[f]));
                asm volatile("ldmatrix.sync.aligned.m8n8.x4.shared.b16 {%0,%1,%2,%3}, [%4];"
                             : "=r"(af[f][0]), "=r"(af[f][1]), "=r"(af[f][2]), "=r"(af[f][3])
                             : "r"(addr));
            }
#pragma unroll
            for (int gp = 0; gp < 2; ++gp) {
                uint32_t bf0, bf1, bf2, bf3;
                uint32_t addr = stb + b_base[gp] +
                                (uint32_t)(16 * ((2 * s + cbit) ^ b_sw[gp]));
                asm volatile("ldmatrix.sync.aligned.m8n8.x4.shared.b16 {%0,%1,%2,%3}, [%4];"
                             : "=r"(bf0), "=r"(bf1), "=r"(bf2), "=r"(bf3)
                             : "r"(addr));
#pragma unroll
                for (int f = 0; f < 4; ++f) {
                    asm volatile(
                        "mma.sync.aligned.m16n8k16.row.col.f32.bf16.bf16.f32 "
                        "{%0,%1,%2,%3}, {%4,%5,%6,%7}, {%8,%9}, {%0,%1,%2,%3};"
                        : "+f"(c[f][2 * gp][0]), "+f"(c[f][2 * gp][1]),
                          "+f"(c[f][2 * gp][2]), "+f"(c[f][2 * gp][3])
                        : "r"(af[f][0]), "r"(af[f][1]), "r"(af[f][2]), "r"(af[f][3]),
                          "r"(bf0), "r"(bf1));
                    asm volatile(
                        "mma.sync.aligned.m16n8k16.row.col.f32.bf16.bf16.f32 "
                        "{%0,%1,%2,%3}, {%4,%5,%6,%7}, {%8,%9}, {%0,%1,%2,%3};"
                        : "+f"(c[f][2 * gp + 1][0]), "+f"(c[f][2 * gp + 1][1]),
                          "+f"(c[f][2 * gp + 1][2]), "+f"(c[f][2 * gp + 1][3])
                        : "r"(af[f][0]), "r"(af[f][1]), "r"(af[f][2]), "r"(af[f][3]),
                          "r"(bf2), "r"(bf3));
                }
            }
        }
    }

    CP_WAIT(0);
    __syncthreads();

    // ---- exact row norms: reduce over the 4 threads sharing a row ----
    {
        float v = ns;
        v += __shfl_xor_sync(0xFFFFFFFFu, v, 1);
        v += __shfl_xor_sync(0xFFFFFFFFu, v, 2);
        if ((tid & 3) == 0) {
            float inv = 1.0f / fmaxf(v, 1e-8f);
            invna_s[arow] = inv;
            if (m0 + arow < U_ROWS) g_inv_na[m0 + arow] = inv;
        }
    }
    __syncthreads();

    // ---- stage scaled sims to Csm[128][257] (reuses stage smem) ----
    float* Csm = (float*)smem;
#pragma unroll
    for (int f = 0; f < 4; ++f) {
        int r0 = mw * 64 + f * 16 + (lane >> 2);
        float na0 = invna_s[r0], na8 = invna_s[r0 + 8];
#pragma unroll
        for (int g = 0; g < 4; ++g) {
            int col = nw * 32 + g * 8 + 2 * (lane & 3);
            float nu0 = invnu_s[col], nu1 = invnu_s[col + 1];
            Csm[r0 * 257 + col]           = c[f][g][0] * na0 * nu0;
            Csm[r0 * 257 + col + 1]       = c[f][g][1] * na0 * nu1;
            Csm[(r0 + 8) * 257 + col]     = c[f][g][2] * na8 * nu0;
            Csm[(r0 + 8) * 257 + col + 1] = c[f][g][3] * na8 * nu1;
        }
    }
    __syncthreads();

    // ---- per-(column, half) top-PK over 64 rows, all 512 threads ----
    unsigned long long* pkb = (unsigned long long*)(smem + OFF_PKBUF);
    {
        const int col = tid & 255;
        const int half = tid >> 8;
        unsigned long long kk[PK];
#pragma unroll
        for (int j = 0; j < PK; j++) kk[j] = 0ull;

        int rbeg = half * 64;
        int rend = rbeg + 64;
        int rmax = U_ROWS - m0;
        if (rend > rmax) rend = rmax;
        for (int r = rbeg; r < rend; ++r) {
            unsigned long long key = okey(Csm[r * 257 + col], m0 + r);
            if (key > kk[PK - 1]) {
                unsigned long long ck = key;
#pragma unroll
                for (int j = 0; j < PK; j++) {
                    if (ck > kk[j]) {
                        unsigned long long t = kk[j];
                        kk[j] = ck; ck = t;
                    }
                }
            }
        }
        unsigned long long* dst = pkb + (size_t)tid * PK;
#pragma unroll
        for (int j = 0; j < PK; j++) dst[j] = kk[j];
    }
    __syncthreads();

    // ---- merge the two sorted halves per column -> g_pk ----
    if (tid < 256) {
        const unsigned long long* a = pkb + (size_t)tid * PK;
        const unsigned long long* bb = pkb + (size_t)(tid + 256) * PK;
        unsigned long long* dst = g_pk + ((size_t)tid * NBLK + blockIdx.x) * PK;
        int p = 0, q = 0;
#pragma unroll
        for (int r = 0; r < PK; ++r) {
            unsigned long long ka = a[p], kb = bb[q];
            bool ta = ka >= kb;
            dst[r] = ta ? ka : kb;
            p += ta; q += !ta;
        }
    }
}

// ---------------- kernel 3: select top-CAND candidates from partials --------
#define SLOCK 8
__global__ void select_cand_kernel() {
    const int b = blockIdx.x;
    const int tid = threadIdx.x;     // 128 threads
    const int lane = tid & 31;
    const int wid = tid >> 5;

    const unsigned long long* src = g_pk + (size_t)b * NBLK * PK;  // 3128 keys

    unsigned long long kk[SLOCK];
#pragma unroll
    for (int j = 0; j < SLOCK; j++) kk[j] = 0ull;

    for (int i = tid; i < NBLK * PK; i += 128) {
        unsigned long long key = src[i];
        if (key > kk[SLOCK - 1]) {
            unsigned long long ck = key;
#pragma unroll
            for (int j = 0; j < SLOCK; j++) {
                if (ck > kk[j]) {
                    unsigned long long t = kk[j];
                    kk[j] = ck; ck = t;
                }
            }
        }
    }

    __shared__ unsigned long long wbest[4];
    __shared__ int wtid[4];
    __shared__ int swin;

    for (int r = 0; r < CAND; ++r) {
        unsigned long long best = kk[0];
        int bt = tid;
#pragma unroll
        for (int o = 16; o > 0; o >>= 1) {
            unsigned long long ob = __shfl_down_sync(0xFFFFFFFFu, best, o);
            int ot = __shfl_down_sync(0xFFFFFFFFu, bt, o);
            if (ob > best) { best = ob; bt = ot; }
        }
        if (lane == 0) { wbest[wid] = best; wtid[wid] = bt; }
        __syncthreads();
        if (tid == 0) {
            unsigned long long m = wbest[0]; int mt = wtid[0];
            for (int i = 1; i < 4; i++)
                if (wbest[i] > m) { m = wbest[i]; mt = wtid[i]; }
            swin = mt;
        }
        __syncthreads();
        if (tid == swin) {
            g_cand_idx[b * CAND + r] = okey_idx(kk[0]);
#pragma unroll
            for (int j = 0; j < SLOCK - 1; j++) kk[j] = kk[j + 1];
            kk[SLOCK - 1] = 0ull;
        }
        __syncthreads();
    }
}

// ---------------- kernel 4: exact fp32 rescore (wide grid) ------------------
// grid = (8, BATCH), 128 threads; warp w of block g rescored candidate g*4+w
__global__ void rescore_kernel(const float* __restrict__ F) {
    const int b = blockIdx.y;
    const int cc = blockIdx.x * 4 + (threadIdx.x >> 5);
    const int lane = threadIdx.x & 31;

    int u = g_cand_idx[b * CAND + cc];
    const float* ub = g_users + (size_t)b * N_ITEMS;
    const float* fu = F + (size_t)u * N_ITEMS;
    float acc = 0.f;
#pragma unroll 4
    for (int k = lane; k < N_ITEMS / 4; k += 32) {
        float4 x = ((const float4*)ub)[k];
        float4 y = ((const float4*)fu)[k];
        acc += x.x * y.x + x.y * y.y + x.z * y.z + x.w * y.w;
    }
    for (int o = 16; o > 0; o >>= 1)
        acc += __shfl_down_sync(0xFFFFFFFFu, acc, o);
    if (lane == 0)
        g_cand_sim[b * CAND + cc] = acc * g_inv_na[u] * g_inv_nu[b];
}

// ---------------- kernel 5: exact top-k + weights ----------------------------
__global__ void finalize_kernel() {
    const int b = blockIdx.x;
    if (threadIdx.x != 0) return;
    const float* ssim = g_cand_sim + b * CAND;
    const int* sidx = g_cand_idx + b * CAND;
    int k = g_k < CAND ? g_k : CAND;
    bool used[CAND];
    for (int i = 0; i < CAND; i++) used[i] = false;
    float s = 0.f;
    float wv[CAND];
    for (int r = 0; r < k; r++) {
        int bi = -1;
        float bv = neg_inf();
        int bidx = 0x7FFFFFFF;
        for (int cc = 0; cc < CAND; cc++) {
            if (used[cc]) continue;
            float v = ssim[cc];
            if (v > bv || (v == bv && sidx[cc] < bidx)) {
                bv = v; bidx = sidx[cc]; bi = cc;
            }
        }
        used[bi] = true;
        wv[r] = bv;
        g_nid[b * MAXK + r] = bidx;
        s += bv;
    }
    float inv = 1.0f / s;
    for (int r = 0; r < k; r++) g_wgt[b * MAXK + r] = wv[r] * inv;
}

// ---------------- kernel 6: weighted neighbor gather ------------------------
__global__ void ratings_kernel(const float* __restrict__ F, float* __restrict__ out) {
    const int b = blockIdx.x;
    const int tid = threadIdx.x;
    const int k = g_k < CAND ? g_k : CAND;

    __shared__ float w[MAXK];
    __shared__ int   id[MAXK];
    if (tid < k) {
        w[tid] = g_wgt[b * MAXK + tid];
        id[tid] = g_nid[b * MAXK + tid];
    }
    __syncthreads();

    for (int i = tid; i < N_ITEMS; i += 256) {
        float acc = 0.f;
        for (int j = 0; j < k; j++)
            acc += w[j] * F[(size_t)id[j] * N_ITEMS + i];
        out[(size_t)b * N_ITEMS + i] = acc;
    }
}

// ---------------- launch ----------------------------------------------------
extern "C" void kernel_launch(void* const* d_in, const int* in_sizes, int n_in,
                              void* d_out, int out_size) {
    const float* F = (const float*)d_in[0];
    const void* ids = d_in[1];
    const int* kptr = (n_in > 2) ? (const int*)d_in[2] : nullptr;

    cudaFuncSetAttribute(gemm_sim_kernel,
                         cudaFuncAttributeMaxDynamicSharedMemorySize, SMEM_TOTAL);

    gather_users_kernel<<<BATCH, 256>>>(F, ids, kptr, kptr != nullptr ? 1 : 0);

    gemm_sim_kernel<<<NBLK, NTHREADS, SMEM_TOTAL>>>(F);

    select_cand_kernel<<<BATCH, 128>>>();
    rescore_kernel<<<dim3(CAND / 4, BATCH), 128>>>(F);
    finalize_kernel<<<BATCH, 32>>>();
    ratings_kernel<<<BATCH, 256>>>(F, (float*)d_out);
}

// round 14
// speedup vs baseline: 1.1393x; 1.1393x over previous
#include <cuda_runtime.h>
#include <cuda_bf16.h>
#include <cstdint>

// Problem constants
#define U_ROWS 50000
#define N_ITEMS 4000
#define BATCH 256
#define MAXK 64
#define CAND 16                 // candidates per row, rescored exactly
#define NBLK 391                // GEMM CTAs = ceil(50000/128)
#define PK 4                    // per-(b, CTA) partial top-k

// GEMM config: CTA tile 128(M) x 256(N), BK=32, 3-stage ring
#define BK 32
#define KITERS (N_ITEMS / BK)   // 125
#define NTHREADS 512            // 16 warps: 2(M) x 8(N), warp tile 64x32

#define STAGE_BYTES 24576       // A bf16 128x64B (8K) + B bf16 256x64B (16K)
// Csm[128][257] floats = 131584 bytes reuses the stage region post-mainloop
#define OFF_INVNA 131584
#define OFF_INVNU (OFF_INVNA + 512)
#define OFF_PKBUF (OFF_INVNU + 1024)        // 512 threads x PK x 8B = 16384
#define SMEM_TOTAL (OFF_PKBUF + 512 * PK * 8 + 64)

// ---------------- scratch (static device memory) ---------------------------
__device__ __align__(16) float g_users[(size_t)BATCH * N_ITEMS];           // 4 MB fp32
__device__ __align__(16) __nv_bfloat16 g_users_bf[(size_t)BATCH * N_ITEMS];// 2 MB
__device__ __align__(16) unsigned long long g_pk[(size_t)BATCH * NBLK * PK]; // 3.2 MB
__device__ float g_inv_na[U_ROWS];
__device__ float g_inv_nu[BATCH];
__device__ int   g_cand_idx[BATCH * CAND];
__device__ int   g_k;

// ---------------- helpers ---------------------------------------------------
__device__ __forceinline__ uint32_t smem_u32(const void* p) {
    uint32_t a;
    asm("{ .reg .u64 t; cvta.to.shared.u64 t, %1; cvt.u32.u64 %0, t; }" : "=r"(a) : "l"(p));
    return a;
}
#define CP_ASYNC16(dst, src) \
    asm volatile("cp.async.cg.shared.global [%0], [%1], 16;" :: "r"(dst), "l"(src))
#define CP_COMMIT() asm volatile("cp.async.commit_group;" ::: "memory")
#define CP_WAIT(n)  asm volatile("cp.async.wait_group %0;" :: "n"(n) : "memory")

__device__ __forceinline__ float neg_inf() { return __int_as_float(0xFF800000); }
__device__ __forceinline__ unsigned bf16u(float x) {
    return (unsigned)__bfloat16_as_ushort(__float2bfloat16_rn(x));
}
__device__ __forceinline__ uint32_t pack_bf2(float a, float b) {
    uint32_t r;
    asm("cvt.rn.bf16x2.f32 %0, %2, %1;" : "=r"(r) : "f"(a), "f"(b));
    return r;
}
// swizzled chunk byte offset within a 64B-row tile
__device__ __forceinline__ uint32_t swz64(int row, int c) {
    return (uint32_t)(row * 64 + 16 * (c ^ ((row >> 1) & 3)));
}
// order-preserving composite key: (value desc, index asc); key > 0 for v >= 0
__device__ __forceinline__ unsigned long long okey(float v, int idx) {
    unsigned kb = __float_as_uint(v);
    kb ^= (kb >> 31) ? 0xFFFFFFFFu : 0x80000000u;
    return ((unsigned long long)kb << 32) |
           (unsigned long long)(0xFFFFFFFFu - (unsigned)idx);
}
__device__ __forceinline__ int okey_idx(unsigned long long k) {
    return (int)(0xFFFFFFFFu - (unsigned)(k & 0xFFFFFFFFull));
}

// ---------------- kernel 1: gather users + norms + mode/k detection ---------
__global__ void gather_users_kernel(const float* __restrict__ F, const void* ids,
                                    const int* kptr, int has_k) {
    const int b = blockIdx.x;
    const int tid = threadIdx.x;

    __shared__ int s_is64;
    if (tid == 0) {
        const unsigned* w = (const unsigned*)ids;
        bool is64 = true;
        for (int i = 0; i < 16; i++)
            if (w[2 * i + 1] != 0u) { is64 = false; break; }
        s_is64 = is64 ? 1 : 0;
        if (b == 0) {
            int kk = 10;
            if (has_k) {
                int vi = kptr[0];
                if (vi >= 1 && vi <= MAXK) kk = vi;
                else {
                    float vf = __int_as_float(vi);
                    if (vf >= 1.f && vf <= (float)MAXK) kk = (int)vf;
                }
            }
            g_k = kk;
        }
    }
    __syncthreads();

    long long uid;
    if (s_is64) uid = ((const long long*)ids)[b];
    else        uid = (long long)((const int*)ids)[b];
    const float4* src = (const float4*)(F + (size_t)uid * N_ITEMS);
    float4* dstf = (float4*)(g_users + (size_t)b * N_ITEMS);
    uint2* dstb = (uint2*)(g_users_bf + (size_t)b * N_ITEMS);
    float s = 0.f;
    for (int v = tid; v < N_ITEMS / 4; v += 256) {
        float4 x = src[v];
        dstf[v] = x;
        uint2 o;
        o.x = bf16u(x.x) | (bf16u(x.y) << 16);
        o.y = bf16u(x.z) | (bf16u(x.w) << 16);
        dstb[v] = o;
        s += x.x * x.x + x.y * x.y + x.z * x.z + x.w * x.w;
    }
    for (int off = 16; off > 0; off >>= 1)
        s += __shfl_down_sync(0xFFFFFFFFu, s, off);
    __shared__ float ws[8];
    if ((tid & 31) == 0) ws[tid >> 5] = s;
    __syncthreads();
    if (tid == 0) {
        float t = 0.f;
        for (int i = 0; i < 8; i++) t += ws[i];
        g_inv_nu[b] = 1.0f / fmaxf(t, 1e-8f);
    }
}

// ---------------- kernel 2: bf16 mma GEMM + fused per-CTA top-PK ------------
__global__ __launch_bounds__(NTHREADS, 1)
void gemm_sim_kernel(const float* __restrict__ F) {
    extern __shared__ __align__(1024) char smem[];
    const uint32_t sbase = smem_u32(smem);
    const int tid = threadIdx.x;
    const int lane = tid & 31;
    const int wid = tid >> 5;
    const int m0 = blockIdx.x * 128;
    const int mw = wid & 1;       // warp M index
    const int nw = wid >> 1;      // warp N index (0..7), warp tile 64x32

    float* invna_s = (float*)(smem + OFF_INVNA);
    float* invnu_s = (float*)(smem + OFF_INVNU);
    if (tid < 256) invnu_s[tid] = g_inv_nu[tid];

    // ---- A producer (fp32 LDG -> cvt -> STS): thread owns (row, 16B chunk) ----
    const int arow = tid >> 2;           // 0..127
    const int ach = tid & 3;             // bf16 16B chunk == fp32 32B chunk
    int gm = m0 + arow; if (gm > U_ROWS - 1) gm = U_ROWS - 1;
    const char* asrc = (const char*)F + (size_t)gm * (N_ITEMS * 4) + ach * 32;
    const uint32_t asts = swz64(arow, ach);

    // ---- B producer (cp.async from bf16 users): rows arow, arow+128 ----
    const char* bsrc0 = (const char*)g_users_bf + (size_t)arow * (N_ITEMS * 2) + ach * 16;
    const char* bsrc1 = bsrc0 + (size_t)128 * (N_ITEMS * 2);
    const uint32_t bst0 = 8192 + swz64(arow, ach);
    const uint32_t bst1 = 8192 + swz64(arow + 128, ach);

    // ---- A fragment (ldmatrix) per-lane constants ----
    const int ahalf = lane >> 4;
    uint32_t a_base[4];
    int a_sw[4];
#pragma unroll
    for (int f = 0; f < 4; f++) {
        int r = mw * 64 + f * 16 + (lane & 15);
        a_base[f] = (uint32_t)(r * 64);
        a_sw[f] = (r >> 1) & 3;
    }
    // ---- B fragment (ldmatrix x4 over 16n x 16k) per-lane constants ----
    const int grp = lane >> 3;
    const int cbit = grp & 1;
    uint32_t b_base[2];
    int b_sw[2];
#pragma unroll
    for (int gp = 0; gp < 2; gp++) {
        int n = nw * 32 + gp * 16 + ((grp & 2) << 2) + (lane & 7);
        b_base[gp] = (uint32_t)(8192 + n * 64);
        b_sw[gp] = (n >> 1) & 3;
    }

    float c[4][4][4];
#pragma unroll
    for (int f = 0; f < 4; f++)
#pragma unroll
        for (int g = 0; g < 4; g++)
#pragma unroll
            for (int i = 0; i < 4; i++) c[f][g][i] = 0.f;

    float ns = 0.f;
    float4 av0, av1;

    auto ldgA = [&](int kt) {
        const char* p = asrc + (size_t)kt * (BK * 4);
        av0 = *(const float4*)p;
        av1 = *(const float4*)(p + 16);
    };
    auto stsA = [&](uint32_t stagebase) {
        ns += av0.x * av0.x + av0.y * av0.y + av0.z * av0.z + av0.w * av0.w;
        ns += av1.x * av1.x + av1.y * av1.y + av1.z * av1.z + av1.w * av1.w;
        uint32_t p0 = pack_bf2(av0.x, av0.y);
        uint32_t p1 = pack_bf2(av0.z, av0.w);
        uint32_t p2 = pack_bf2(av1.x, av1.y);
        uint32_t p3 = pack_bf2(av1.z, av1.w);
        asm volatile("st.shared.v4.b32 [%0], {%1,%2,%3,%4};"
                     :: "r"(stagebase + asts), "r"(p0), "r"(p1), "r"(p2), "r"(p3)
                     : "memory");
    };
    auto issueB = [&](int kt) {
        uint32_t stb = sbase + (kt % 3) * STAGE_BYTES;
        CP_ASYNC16(stb + bst0, bsrc0 + (size_t)kt * (BK * 2));
        CP_ASYNC16(stb + bst1, bsrc1 + (size_t)kt * (BK * 2));
    };

    // ---- prologue ----
    issueB(0); CP_COMMIT();
    issueB(1); CP_COMMIT();
    ldgA(0);
    stsA(sbase);
    ldgA(1);

    // ---- mainloop ----
    for (int kt = 0; kt < KITERS; ++kt) {
        CP_WAIT(1);
        __syncthreads();
        if (kt + 2 < KITERS) issueB(kt + 2);
        CP_COMMIT();
        if (kt + 1 < KITERS) stsA(sbase + ((kt + 1) % 3) * STAGE_BYTES);
        if (kt + 2 < KITERS) ldgA(kt + 2);

        const uint32_t stb = sbase + (kt % 3) * STAGE_BYTES;
#pragma unroll
        for (int s = 0; s < 2; ++s) {
            uint32_t af[4][4];
#pragma unroll
            for (int f = 0; f < 4; ++f) {
                uint32_t addr = stb + a_base[f] +
                                (uint32_t)(16 * ((2 * s + ahalf) ^ a_sw[f]));
                asm volatile("ldmatrix.sync.aligned.m8n8.x4.shared.b16 {%0,%1,%2,%3}, [%4];"
                             : "=r"(af[f][0]), "=r"(af[f][1]), "=r"(af[f][2]), "=r"(af[f][3])
                             : "r"(addr));
            }
#pragma unroll
            for (int gp = 0; gp < 2; ++gp) {
                uint32_t bf0, bf1, bf2, bf3;
                uint32_t addr = stb + b_base[gp] +
                                (uint32_t)(16 * ((2 * s + cbit) ^ b_sw[gp]));
                asm volatile("ldmatrix.sync.aligned.m8n8.x4.shared.b16 {%0,%1,%2,%3}, [%4];"
                             : "=r"(bf0), "=r"(bf1), "=r"(bf2), "=r"(bf3)
                             : "r"(addr));
#pragma unroll
                for (int f = 0; f < 4; ++f) {
                    asm volatile(
                        "mma.sync.aligned.m16n8k16.row.col.f32.bf16.bf16.f32 "
                        "{%0,%1,%2,%3}, {%4,%5,%6,%7}, {%8,%9}, {%0,%1,%2,%3};"
                        : "+f"(c[f][2 * gp][0]), "+f"(c[f][2 * gp][1]),
                          "+f"(c[f][2 * gp][2]), "+f"(c[f][2 * gp][3])
                        : "r"(af[f][0]), "r"(af[f][1]), "r"(af[f][2]), "r"(af[f][3]),
                          "r"(bf0), "r"(bf1));
                    asm volatile(
                        "mma.sync.aligned.m16n8k16.row.col.f32.bf16.bf16.f32 "
                        "{%0,%1,%2,%3}, {%4,%5,%6,%7}, {%8,%9}, {%0,%1,%2,%3};"
                        : "+f"(c[f][2 * gp + 1][0]), "+f"(c[f][2 * gp + 1][1]),
                          "+f"(c[f][2 * gp + 1][2]), "+f"(c[f][2 * gp + 1][3])
                        : "r"(af[f][0]), "r"(af[f][1]), "r"(af[f][2]), "r"(af[f][3]),
                          "r"(bf2), "r"(bf3));
                }
            }
        }
    }

    CP_WAIT(0);
    __syncthreads();

    // ---- exact row norms: reduce over the 4 threads sharing a row ----
    {
        float v = ns;
        v += __shfl_xor_sync(0xFFFFFFFFu, v, 1);
        v += __shfl_xor_sync(0xFFFFFFFFu, v, 2);
        if ((tid & 3) == 0) {
            float inv = 1.0f / fmaxf(v, 1e-8f);
            invna_s[arow] = inv;
            if (m0 + arow < U_ROWS) g_inv_na[m0 + arow] = inv;
        }
    }
    __syncthreads();

    // ---- stage scaled sims to Csm[128][257] (reuses stage smem) ----
    float* Csm = (float*)smem;
#pragma unroll
    for (int f = 0; f < 4; ++f) {
        int r0 = mw * 64 + f * 16 + (lane >> 2);
        float na0 = invna_s[r0], na8 = invna_s[r0 + 8];
#pragma unroll
        for (int g = 0; g < 4; ++g) {
            int col = nw * 32 + g * 8 + 2 * (lane & 3);
            float nu0 = invnu_s[col], nu1 = invnu_s[col + 1];
            Csm[r0 * 257 + col]           = c[f][g][0] * na0 * nu0;
            Csm[r0 * 257 + col + 1]       = c[f][g][1] * na0 * nu1;
            Csm[(r0 + 8) * 257 + col]     = c[f][g][2] * na8 * nu0;
            Csm[(r0 + 8) * 257 + col + 1] = c[f][g][3] * na8 * nu1;
        }
    }
    __syncthreads();

    // ---- per-(column, half) top-PK over 64 rows, all 512 threads ----
    unsigned long long* pkb = (unsigned long long*)(smem + OFF_PKBUF);
    {
        const int col = tid & 255;
        const int half = tid >> 8;
        unsigned long long kk[PK];
#pragma unroll
        for (int j = 0; j < PK; j++) kk[j] = 0ull;

        int rbeg = half * 64;
        int rend = rbeg + 64;
        int rmax = U_ROWS - m0;
        if (rend > rmax) rend = rmax;
        for (int r = rbeg; r < rend; ++r) {
            unsigned long long key = okey(Csm[r * 257 + col], m0 + r);
            if (key > kk[PK - 1]) {
                unsigned long long ck = key;
#pragma unroll
                for (int j = 0; j < PK; j++) {
                    if (ck > kk[j]) {
                        unsigned long long t = kk[j];
                        kk[j] = ck; ck = t;
                    }
                }
            }
        }
        unsigned long long* dst = pkb + (size_t)tid * PK;
#pragma unroll
        for (int j = 0; j < PK; j++) dst[j] = kk[j];
    }
    __syncthreads();

    // ---- merge the two sorted halves per column -> g_pk ----
    if (tid < 256) {
        const unsigned long long* a = pkb + (size_t)tid * PK;
        const unsigned long long* bb = pkb + (size_t)(tid + 256) * PK;
        unsigned long long* dst = g_pk + ((size_t)tid * NBLK + blockIdx.x) * PK;
        int p = 0, q = 0;
#pragma unroll
        for (int r = 0; r < PK; ++r) {
            unsigned long long ka = a[p], kb = bb[q];
            bool ta = ka >= kb;
            dst[r] = ta ? ka : kb;
            p += ta; q += !ta;
        }
    }
}

// ---------------- kernel 3: select top-CAND candidates from partials --------
#define SLOCK 8
__global__ void select_cand_kernel() {
    const int b = blockIdx.x;
    const int tid = threadIdx.x;     // 128 threads
    const int lane = tid & 31;
    const int wid = tid >> 5;

    const unsigned long long* src = g_pk + (size_t)b * NBLK * PK;  // 1564 keys

    unsigned long long kk[SLOCK];
#pragma unroll
    for (int j = 0; j < SLOCK; j++) kk[j] = 0ull;

    for (int i = tid; i < NBLK * PK; i += 128) {
        unsigned long long key = src[i];
        if (key > kk[SLOCK - 1]) {
            unsigned long long ck = key;
#pragma unroll
            for (int j = 0; j < SLOCK; j++) {
                if (ck > kk[j]) {
                    unsigned long long t = kk[j];
                    kk[j] = ck; ck = t;
                }
            }
        }
    }

    __shared__ unsigned long long wbest[4];
    __shared__ int wtid[4];
    __shared__ int swin;

    for (int r = 0; r < CAND; ++r) {
        unsigned long long best = kk[0];
        int bt = tid;
#pragma unroll
        for (int o = 16; o > 0; o >>= 1) {
            unsigned long long ob = __shfl_down_sync(0xFFFFFFFFu, best, o);
            int ot = __shfl_down_sync(0xFFFFFFFFu, bt, o);
            if (ob > best) { best = ob; bt = ot; }
        }
        if (lane == 0) { wbest[wid] = best; wtid[wid] = bt; }
        __syncthreads();
        if (tid == 0) {
            unsigned long long m = wbest[0]; int mt = wtid[0];
            for (int i = 1; i < 4; i++)
                if (wbest[i] > m) { m = wbest[i]; mt = wtid[i]; }
            swin = mt;
        }
        __syncthreads();
        if (tid == swin) {
            g_cand_idx[b * CAND + r] = okey_idx(kk[0]);
#pragma unroll
            for (int j = 0; j < SLOCK - 1; j++) kk[j] = kk[j + 1];
            kk[SLOCK - 1] = 0ull;
        }
        __syncthreads();
    }
}

// ---------------- kernel 4: exact fp32 rescore + top-k + ratings ------------
__global__ void rescore_ratings_kernel(const float* __restrict__ F,
                                       float* __restrict__ out) {
    const int b = blockIdx.x;
    const int tid = threadIdx.x;     // 256 threads
    const int lane = tid & 31;
    const int w = tid >> 5;

    __shared__ float ssim[CAND];
    __shared__ int   sidx[CAND];
    __shared__ float wgt[CAND];
    __shared__ int   nid[CAND];

    // ---- exact rescore of CAND candidates (8 warps x 2) ----
    {
        const float* ub = g_users + (size_t)b * N_ITEMS;
        const float inv_nu = g_inv_nu[b];
        for (int cc = w; cc < CAND; cc += 8) {
            int u = g_cand_idx[b * CAND + cc];
            const float* fu = F + (size_t)u * N_ITEMS;
            float acc = 0.f;
            for (int k = lane; k < N_ITEMS / 4; k += 32) {
                float4 x = ((const float4*)ub)[k];
                float4 y = ((const float4*)fu)[k];
                acc += x.x * y.x + x.y * y.y + x.z * y.z + x.w * y.w;
            }
            for (int o = 16; o > 0; o >>= 1)
                acc += __shfl_down_sync(0xFFFFFFFFu, acc, o);
            if (lane == 0) {
                ssim[cc] = acc * g_inv_na[u] * inv_nu;
                sidx[cc] = u;
            }
        }
    }
    __syncthreads();

    // ---- exact top-k with jax tie-break + weights (thread 0; k small) ----
    if (tid == 0) {
        int k = g_k < CAND ? g_k : CAND;
        bool used[CAND];
        for (int i = 0; i < CAND; i++) used[i] = false;
        float s = 0.f;
        for (int r = 0; r < k; r++) {
            int bi = -1;
            float bv = neg_inf();
            int bidx = 0x7FFFFFFF;
            for (int cc = 0; cc < CAND; cc++) {
                if (used[cc]) continue;
                float v = ssim[cc];
                if (v > bv || (v == bv && sidx[cc] < bidx)) {
                    bv = v; bidx = sidx[cc]; bi = cc;
                }
            }
            used[bi] = true;
            wgt[r] = bv;
            nid[r] = bidx;
            s += bv;
        }
        float inv = 1.0f / s;
        for (int r = 0; r < k; r++) wgt[r] *= inv;
    }
    __syncthreads();

    // ---- weighted neighbor gather ----
    {
        int k = g_k < CAND ? g_k : CAND;
        for (int i = tid; i < N_ITEMS; i += 256) {
            float acc = 0.f;
            for (int j = 0; j < k; j++)
                acc += wgt[j] * F[(size_t)nid[j] * N_ITEMS + i];
            out[(size_t)b * N_ITEMS + i] = acc;
        }
    }
}

// ---------------- launch ----------------------------------------------------
extern "C" void kernel_launch(void* const* d_in, const int* in_sizes, int n_in,
                              void* d_out, int out_size) {
    const float* F = (const float*)d_in[0];
    const void* ids = d_in[1];
    const int* kptr = (n_in > 2) ? (const int*)d_in[2] : nullptr;

    cudaFuncSetAttribute(gemm_sim_kernel,
                         cudaFuncAttributeMaxDynamicSharedMemorySize, SMEM_TOTAL);

    gather_users_kernel<<<BATCH, 256>>>(F, ids, kptr, kptr != nullptr ? 1 : 0);

    gemm_sim_kernel<<<NBLK, NTHREADS, SMEM_TOTAL>>>(F);

    select_cand_kernel<<<BATCH, 128>>>();
    rescore_ratings_kernel<<<BATCH, 256>>>(F, (float*)d_out);
}

// round 15
// speedup vs baseline: 1.1713x; 1.0282x over previous
#include <cuda_runtime.h>
#include <cuda_bf16.h>
#include <cstdint>

// Problem constants
#define U_ROWS 50000
#define N_ITEMS 4000
#define BATCH 256
#define MAXK 64
#define CAND 16                 // candidates per row, rescored exactly
#define NBLK 391                // GEMM CTAs = ceil(50000/128)
#define PK 4                    // per-(b, CTA) partial top-k

// GEMM config: CTA tile 128(M) x 256(N), BK=32, 3-stage ring
#define BK 32
#define KITERS (N_ITEMS / BK)   // 125
#define NTHREADS 512            // 16 warps: 2(M) x 8(N), warp tile 64x32

#define STAGE_BYTES 24576       // A bf16 128x64B (8K) + B bf16 256x64B (16K)
// Csm[128][257] floats = 131584 bytes reuses the stage region post-mainloop
#define OFF_INVNA 131584
#define OFF_INVNU (OFF_INVNA + 512)
#define OFF_PKBUF (OFF_INVNU + 1024)        // 512 threads x PK x 8B = 16384
#define SMEM_TOTAL (OFF_PKBUF + 512 * PK * 8 + 64)

// ---------------- scratch (static device memory) ---------------------------
__device__ __align__(16) float g_users[(size_t)BATCH * N_ITEMS];           // 4 MB fp32
__device__ __align__(16) __nv_bfloat16 g_users_bf[(size_t)BATCH * N_ITEMS];// 2 MB
__device__ __align__(16) unsigned long long g_pk[(size_t)BATCH * NBLK * PK]; // 3.2 MB
__device__ float g_inv_na[U_ROWS];
__device__ float g_inv_nu[BATCH];
__device__ int   g_cand_idx[BATCH * CAND];
__device__ int   g_k;

// ---------------- helpers ---------------------------------------------------
__device__ __forceinline__ uint32_t smem_u32(const void* p) {
    uint32_t a;
    asm("{ .reg .u64 t; cvta.to.shared.u64 t, %1; cvt.u32.u64 %0, t; }" : "=r"(a) : "l"(p));
    return a;
}
#define CP_ASYNC16(dst, src) \
    asm volatile("cp.async.cg.shared.global [%0], [%1], 16;" :: "r"(dst), "l"(src))
#define CP_COMMIT() asm volatile("cp.async.commit_group;" ::: "memory")
#define CP_WAIT(n)  asm volatile("cp.async.wait_group %0;" :: "n"(n) : "memory")

__device__ __forceinline__ float neg_inf() { return __int_as_float(0xFF800000); }
__device__ __forceinline__ unsigned bf16u(float x) {
    return (unsigned)__bfloat16_as_ushort(__float2bfloat16_rn(x));
}
__device__ __forceinline__ uint32_t pack_bf2(float a, float b) {
    uint32_t r;
    asm("cvt.rn.bf16x2.f32 %0, %2, %1;" : "=r"(r) : "f"(a), "f"(b));
    return r;
}
// swizzled chunk byte offset within a 64B-row tile
__device__ __forceinline__ uint32_t swz64(int row, int c) {
    return (uint32_t)(row * 64 + 16 * (c ^ ((row >> 1) & 3)));
}
// order-preserving composite key: (value desc, index asc); key > 0 for v >= 0
__device__ __forceinline__ unsigned long long okey(float v, int idx) {
    unsigned kb = __float_as_uint(v);
    kb ^= (kb >> 31) ? 0xFFFFFFFFu : 0x80000000u;
    return ((unsigned long long)kb << 32) |
           (unsigned long long)(0xFFFFFFFFu - (unsigned)idx);
}
__device__ __forceinline__ int okey_idx(unsigned long long k) {
    return (int)(0xFFFFFFFFu - (unsigned)(k & 0xFFFFFFFFull));
}

// ---------------- kernel 1: gather users + norms + mode/k detection ---------
__global__ void gather_users_kernel(const float* __restrict__ F, const void* ids,
                                    const int* kptr, int has_k) {
    const int b = blockIdx.x;
    const int tid = threadIdx.x;   // 512 threads

    __shared__ int s_is64;
    if (tid == 0) {
        const unsigned* w = (const unsigned*)ids;
        bool is64 = true;
        for (int i = 0; i < 16; i++)
            if (w[2 * i + 1] != 0u) { is64 = false; break; }
        s_is64 = is64 ? 1 : 0;
        if (b == 0) {
            int kk = 10;
            if (has_k) {
                int vi = kptr[0];
                if (vi >= 1 && vi <= MAXK) kk = vi;
                else {
                    float vf = __int_as_float(vi);
                    if (vf >= 1.f && vf <= (float)MAXK) kk = (int)vf;
                }
            }
            g_k = kk;
        }
    }
    __syncthreads();

    long long uid;
    if (s_is64) uid = ((const long long*)ids)[b];
    else        uid = (long long)((const int*)ids)[b];
    const float4* src = (const float4*)(F + (size_t)uid * N_ITEMS);
    float4* dstf = (float4*)(g_users + (size_t)b * N_ITEMS);
    uint2* dstb = (uint2*)(g_users_bf + (size_t)b * N_ITEMS);
    float s = 0.f;
    for (int v = tid; v < N_ITEMS / 4; v += 512) {
        float4 x = src[v];
        dstf[v] = x;
        uint2 o;
        o.x = bf16u(x.x) | (bf16u(x.y) << 16);
        o.y = bf16u(x.z) | (bf16u(x.w) << 16);
        dstb[v] = o;
        s += x.x * x.x + x.y * x.y + x.z * x.z + x.w * x.w;
    }
    for (int off = 16; off > 0; off >>= 1)
        s += __shfl_down_sync(0xFFFFFFFFu, s, off);
    __shared__ float ws[16];
    if ((tid & 31) == 0) ws[tid >> 5] = s;
    __syncthreads();
    if (tid == 0) {
        float t = 0.f;
        for (int i = 0; i < 16; i++) t += ws[i];
        g_inv_nu[b] = 1.0f / fmaxf(t, 1e-8f);
    }
}

// ---------------- kernel 2: bf16 mma GEMM + fused per-CTA top-PK ------------
__global__ __launch_bounds__(NTHREADS, 1)
void gemm_sim_kernel(const float* __restrict__ F) {
    extern __shared__ __align__(1024) char smem[];
    const uint32_t sbase = smem_u32(smem);
    const int tid = threadIdx.x;
    const int lane = tid & 31;
    const int wid = tid >> 5;
    const int m0 = blockIdx.x * 128;
    const int mw = wid & 1;       // warp M index
    const int nw = wid >> 1;      // warp N index (0..7), warp tile 64x32

    float* invna_s = (float*)(smem + OFF_INVNA);
    float* invnu_s = (float*)(smem + OFF_INVNU);
    if (tid < 256) invnu_s[tid] = g_inv_nu[tid];

    // ---- A producer (fp32 LDG -> cvt -> STS): thread owns (row, 16B chunk) ----
    const int arow = tid >> 2;           // 0..127
    const int ach = tid & 3;             // bf16 16B chunk == fp32 32B chunk
    int gm = m0 + arow; if (gm > U_ROWS - 1) gm = U_ROWS - 1;
    const char* asrc = (const char*)F + (size_t)gm * (N_ITEMS * 4) + ach * 32;
    const uint32_t asts = swz64(arow, ach);

    // ---- B producer (cp.async from bf16 users): rows arow, arow+128 ----
    const char* bsrc0 = (const char*)g_users_bf + (size_t)arow * (N_ITEMS * 2) + ach * 16;
    const char* bsrc1 = bsrc0 + (size_t)128 * (N_ITEMS * 2);
    const uint32_t bst0 = 8192 + swz64(arow, ach);
    const uint32_t bst1 = 8192 + swz64(arow + 128, ach);

    // ---- A fragment (ldmatrix) per-lane constants ----
    const int ahalf = lane >> 4;
    uint32_t a_base[4];
    int a_sw[4];
#pragma unroll
    for (int f = 0; f < 4; f++) {
        int r = mw * 64 + f * 16 + (lane & 15);
        a_base[f] = (uint32_t)(r * 64);
        a_sw[f] = (r >> 1) & 3;
    }
    // ---- B fragment (ldmatrix x4 over 16n x 16k) per-lane constants ----
    const int grp = lane >> 3;
    const int cbit = grp & 1;
    uint32_t b_base[2];
    int b_sw[2];
#pragma unroll
    for (int gp = 0; gp < 2; gp++) {
        int n = nw * 32 + gp * 16 + ((grp & 2) << 2) + (lane & 7);
        b_base[gp] = (uint32_t)(8192 + n * 64);
        b_sw[gp] = (n >> 1) & 3;
    }

    float c[4][4][4];
#pragma unroll
    for (int f = 0; f < 4; f++)
#pragma unroll
        for (int g = 0; g < 4; g++)
#pragma unroll
            for (int i = 0; i < 4; i++) c[f][g][i] = 0.f;

    float ns = 0.f;
    float4 av0, av1;

    auto ldgA = [&](int kt) {
        const char* p = asrc + (size_t)kt * (BK * 4);
        av0 = *(const float4*)p;
        av1 = *(const float4*)(p + 16);
    };
    auto stsA = [&](uint32_t stagebase) {
        ns += av0.x * av0.x + av0.y * av0.y + av0.z * av0.z + av0.w * av0.w;
        ns += av1.x * av1.x + av1.y * av1.y + av1.z * av1.z + av1.w * av1.w;
        uint32_t p0 = pack_bf2(av0.x, av0.y);
        uint32_t p1 = pack_bf2(av0.z, av0.w);
        uint32_t p2 = pack_bf2(av1.x, av1.y);
        uint32_t p3 = pack_bf2(av1.z, av1.w);
        asm volatile("st.shared.v4.b32 [%0], {%1,%2,%3,%4};"
                     :: "r"(stagebase + asts), "r"(p0), "r"(p1), "r"(p2), "r"(p3)
                     : "memory");
    };
    auto issueB = [&](int kt) {
        uint32_t stb = sbase + (kt % 3) * STAGE_BYTES;
        CP_ASYNC16(stb + bst0, bsrc0 + (size_t)kt * (BK * 2));
        CP_ASYNC16(stb + bst1, bsrc1 + (size_t)kt * (BK * 2));
    };

    // ---- prologue ----
    issueB(0); CP_COMMIT();
    issueB(1); CP_COMMIT();
    ldgA(0);
    stsA(sbase);
    ldgA(1);

    // ---- mainloop ----
    for (int kt = 0; kt < KITERS; ++kt) {
        CP_WAIT(1);
        __syncthreads();
        if (kt + 2 < KITERS) issueB(kt + 2);
        CP_COMMIT();
        if (kt + 1 < KITERS) stsA(sbase + ((kt + 1) % 3) * STAGE_BYTES);
        if (kt + 2 < KITERS) ldgA(kt + 2);

        const uint32_t stb = sbase + (kt % 3) * STAGE_BYTES;
#pragma unroll
        for (int s = 0; s < 2; ++s) {
            uint32_t af[4][4];
#pragma unroll
            for (int f = 0; f < 4; ++f) {
                uint32_t addr = stb + a_base[f] +
                                (uint32_t)(16 * ((2 * s + ahalf) ^ a_sw[f]));
                asm volatile("ldmatrix.sync.aligned.m8n8.x4.shared.b16 {%0,%1,%2,%3}, [%4];"
                             : "=r"(af[f][0]), "=r"(af[f][1]), "=r"(af[f][2]), "=r"(af[f][3])
                             : "r"(addr));
            }
#pragma unroll
            for (int gp = 0; gp < 2; ++gp) {
                uint32_t bf0, bf1, bf2, bf3;
                uint32_t addr = stb + b_base[gp] +
                                (uint32_t)(16 * ((2 * s + cbit) ^ b_sw[gp]));
                asm volatile("ldmatrix.sync.aligned.m8n8.x4.shared.b16 {%0,%1,%2,%3}, [%4];"
                             : "=r"(bf0), "=r"(bf1), "=r"(bf2), "=r"(bf3)
                             : "r"(addr));
#pragma unroll
                for (int f = 0; f < 4; ++f) {
                    asm volatile(
                        "mma.sync.aligned.m16n8k16.row.col.f32.bf16.bf16.f32 "
                        "{%0,%1,%2,%3}, {%4,%5,%6,%7}, {%8,%9}, {%0,%1,%2,%3};"
                        : "+f"(c[f][2 * gp][0]), "+f"(c[f][2 * gp][1]),
                          "+f"(c[f][2 * gp][2]), "+f"(c[f][2 * gp][3])
                        : "r"(af[f][0]), "r"(af[f][1]), "r"(af[f][2]), "r"(af[f][3]),
                          "r"(bf0), "r"(bf1));
                    asm volatile(
                        "mma.sync.aligned.m16n8k16.row.col.f32.bf16.bf16.f32 "
                        "{%0,%1,%2,%3}, {%4,%5,%6,%7}, {%8,%9}, {%0,%1,%2,%3};"
                        : "+f"(c[f][2 * gp + 1][0]), "+f"(c[f][2 * gp + 1][1]),
                          "+f"(c[f][2 * gp + 1][2]), "+f"(c[f][2 * gp + 1][3])
                        : "r"(af[f][0]), "r"(af[f][1]), "r"(af[f][2]), "r"(af[f][3]),
                          "r"(bf2), "r"(bf3));
                }
            }
        }
    }

    CP_WAIT(0);
    __syncthreads();

    // ---- exact row norms: reduce over the 4 threads sharing a row ----
    {
        float v = ns;
        v += __shfl_xor_sync(0xFFFFFFFFu, v, 1);
        v += __shfl_xor_sync(0xFFFFFFFFu, v, 2);
        if ((tid & 3) == 0) {
            float inv = 1.0f / fmaxf(v, 1e-8f);
            invna_s[arow] = inv;
            if (m0 + arow < U_ROWS) g_inv_na[m0 + arow] = inv;
        }
    }
    __syncthreads();

    // ---- stage scaled sims to Csm[128][257] (reuses stage smem) ----
    float* Csm = (float*)smem;
#pragma unroll
    for (int f = 0; f < 4; ++f) {
        int r0 = mw * 64 + f * 16 + (lane >> 2);
        float na0 = invna_s[r0], na8 = invna_s[r0 + 8];
#pragma unroll
        for (int g = 0; g < 4; ++g) {
            int col = nw * 32 + g * 8 + 2 * (lane & 3);
            float nu0 = invnu_s[col], nu1 = invnu_s[col + 1];
            Csm[r0 * 257 + col]           = c[f][g][0] * na0 * nu0;
            Csm[r0 * 257 + col + 1]       = c[f][g][1] * na0 * nu1;
            Csm[(r0 + 8) * 257 + col]     = c[f][g][2] * na8 * nu0;
            Csm[(r0 + 8) * 257 + col + 1] = c[f][g][3] * na8 * nu1;
        }
    }
    __syncthreads();

    // ---- per-(column, half) top-PK over 64 rows, all 512 threads ----
    unsigned long long* pkb = (unsigned long long*)(smem + OFF_PKBUF);
    {
        const int col = tid & 255;
        const int half = tid >> 8;
        unsigned long long kk[PK];
#pragma unroll
        for (int j = 0; j < PK; j++) kk[j] = 0ull;

        int rbeg = half * 64;
        int rend = rbeg + 64;
        int rmax = U_ROWS - m0;
        if (rend > rmax) rend = rmax;
        for (int r = rbeg; r < rend; ++r) {
            unsigned long long key = okey(Csm[r * 257 + col], m0 + r);
            if (key > kk[PK - 1]) {
                unsigned long long ck = key;
#pragma unroll
                for (int j = 0; j < PK; j++) {
                    if (ck > kk[j]) {
                        unsigned long long t = kk[j];
                        kk[j] = ck; ck = t;
                    }
                }
            }
        }
        unsigned long long* dst = pkb + (size_t)tid * PK;
#pragma unroll
        for (int j = 0; j < PK; j++) dst[j] = kk[j];
    }
    __syncthreads();

    // ---- merge the two sorted halves per column -> g_pk ----
    if (tid < 256) {
        const unsigned long long* a = pkb + (size_t)tid * PK;
        const unsigned long long* bb = pkb + (size_t)(tid + 256) * PK;
        unsigned long long* dst = g_pk + ((size_t)tid * NBLK + blockIdx.x) * PK;
        int p = 0, q = 0;
#pragma unroll
        for (int r = 0; r < PK; ++r) {
            unsigned long long ka = a[p], kb = bb[q];
            bool ta = ka >= kb;
            dst[r] = ta ? ka : kb;
            p += ta; q += !ta;
        }
    }
}

// ---------------- kernel 3: select top-CAND candidates from partials --------
#define SLOCK 8
__global__ void select_cand_kernel() {
    const int b = blockIdx.x;
    const int tid = threadIdx.x;     // 128 threads
    const int lane = tid & 31;
    const int wid = tid >> 5;

    const unsigned long long* src = g_pk + (size_t)b * NBLK * PK;  // 1564 keys

    unsigned long long kk[SLOCK];
#pragma unroll
    for (int j = 0; j < SLOCK; j++) kk[j] = 0ull;

    for (int i = tid; i < NBLK * PK; i += 128) {
        unsigned long long key = src[i];
        if (key > kk[SLOCK - 1]) {
            unsigned long long ck = key;
#pragma unroll
            for (int j = 0; j < SLOCK; j++) {
                if (ck > kk[j]) {
                    unsigned long long t = kk[j];
                    kk[j] = ck; ck = t;
                }
            }
        }
    }

    __shared__ unsigned long long wbest[4];
    __shared__ int wtid[4];
    __shared__ int swin;

    for (int r = 0; r < CAND; ++r) {
        unsigned long long best = kk[0];
        int bt = tid;
#pragma unroll
        for (int o = 16; o > 0; o >>= 1) {
            unsigned long long ob = __shfl_down_sync(0xFFFFFFFFu, best, o);
            int ot = __shfl_down_sync(0xFFFFFFFFu, bt, o);
            if (ob > best) { best = ob; bt = ot; }
        }
        if (lane == 0) { wbest[wid] = best; wtid[wid] = bt; }
        __syncthreads();
        if (tid == 0) {
            unsigned long long m = wbest[0]; int mt = wtid[0];
            for (int i = 1; i < 4; i++)
                if (wbest[i] > m) { m = wbest[i]; mt = wtid[i]; }
            swin = mt;
        }
        __syncthreads();
        if (tid == swin) {
            g_cand_idx[b * CAND + r] = okey_idx(kk[0]);
#pragma unroll
            for (int j = 0; j < SLOCK - 1; j++) kk[j] = kk[j + 1];
            kk[SLOCK - 1] = 0ull;
        }
        __syncthreads();
    }
}

// ---------------- kernel 4: exact fp32 rescore + top-k + ratings ------------
__global__ void rescore_ratings_kernel(const float* __restrict__ F,
                                       float* __restrict__ out) {
    const int b = blockIdx.x;
    const int tid = threadIdx.x;     // 512 threads = 16 warps
    const int lane = tid & 31;
    const int w = tid >> 5;

    __shared__ float ssim[CAND];
    __shared__ int   sidx[CAND];
    __shared__ float wgt[CAND];
    __shared__ int   nid[CAND];

    // ---- exact rescore: one warp per candidate (16 warps = CAND) ----
    {
        const float* ub = g_users + (size_t)b * N_ITEMS;
        const float inv_nu = g_inv_nu[b];
        int u = g_cand_idx[b * CAND + w];
        const float* fu = F + (size_t)u * N_ITEMS;
        float acc = 0.f;
#pragma unroll 4
        for (int k = lane; k < N_ITEMS / 4; k += 32) {
            float4 x = ((const float4*)ub)[k];
            float4 y = ((const float4*)fu)[k];
            acc += x.x * y.x + x.y * y.y + x.z * y.z + x.w * y.w;
        }
        for (int o = 16; o > 0; o >>= 1)
            acc += __shfl_down_sync(0xFFFFFFFFu, acc, o);
        if (lane == 0) {
            ssim[w] = acc * g_inv_na[u] * inv_nu;
            sidx[w] = u;
        }
    }
    __syncthreads();

    // ---- exact top-k with jax tie-break + weights (thread 0; k small) ----
    if (tid == 0) {
        int k = g_k < CAND ? g_k : CAND;
        bool used[CAND];
        for (int i = 0; i < CAND; i++) used[i] = false;
        float s = 0.f;
        for (int r = 0; r < k; r++) {
            int bi = -1;
            float bv = neg_inf();
            int bidx = 0x7FFFFFFF;
            for (int cc = 0; cc < CAND; cc++) {
                if (used[cc]) continue;
                float v = ssim[cc];
                if (v > bv || (v == bv && sidx[cc] < bidx)) {
                    bv = v; bidx = sidx[cc]; bi = cc;
                }
            }
            used[bi] = true;
            wgt[r] = bv;
            nid[r] = bidx;
            s += bv;
        }
        float inv = 1.0f / s;
        for (int r = 0; r < k; r++) wgt[r] *= inv;
    }
    __syncthreads();

    // ---- weighted neighbor gather (512 threads) ----
    {
        int k = g_k < CAND ? g_k : CAND;
        for (int i = tid; i < N_ITEMS; i += 512) {
            float acc = 0.f;
            for (int j = 0; j < k; j++)
                acc += wgt[j] * F[(size_t)nid[j] * N_ITEMS + i];
            out[(size_t)b * N_ITEMS + i] = acc;
        }
    }
}

// ---------------- launch ----------------------------------------------------
extern "C" void kernel_launch(void* const* d_in, const int* in_sizes, int n_in,
                              void* d_out, int out_size) {
    const float* F = (const float*)d_in[0];
    const void* ids = d_in[1];
    const int* kptr = (n_in > 2) ? (const int*)d_in[2] : nullptr;

    cudaFuncSetAttribute(gemm_sim_kernel,
                         cudaFuncAttributeMaxDynamicSharedMemorySize, SMEM_TOTAL);

    gather_users_kernel<<<BATCH, 512>>>(F, ids, kptr, kptr != nullptr ? 1 : 0);

    gemm_sim_kernel<<<NBLK, NTHREADS, SMEM_TOTAL>>>(F);

    select_cand_kernel<<<BATCH, 128>>>();
    rescore_ratings_kernel<<<BATCH, 512>>>(F, (float*)d_out);
}

// round 17
// speedup vs baseline: 1.1778x; 1.0055x over previous
#include <cuda_runtime.h>
#include <cuda_bf16.h>
#include <cstdint>

// Problem constants
#define U_ROWS 50000
#define N_ITEMS 4000
#define BATCH 256
#define MAXK 64
#define CAND 16                 // candidates per row, rescored exactly
#define NBLK 391                // GEMM CTAs = ceil(50000/128)
#define PK 4                    // per-(b, CTA) partial top-k

// GEMM config: CTA tile 128(M) x 256(N), BK=32, 3-stage ring
#define BK 32
#define KITERS (N_ITEMS / BK)   // 125
#define NTHREADS 512            // 16 warps: 2(M) x 8(N), warp tile 64x32

#define STAGE_BYTES 24576       // A bf16 128x64B (8K) + B bf16 256x64B (16K)
// Csm[128][257] floats = 131584 bytes reuses the stage region post-mainloop
#define OFF_INVNA 131584
#define OFF_INVNU (OFF_INVNA + 512)
#define OFF_PKBUF (OFF_INVNU + 1024)        // 512 threads x PK x 8B = 16384
#define SMEM_TOTAL (OFF_PKBUF + 512 * PK * 8 + 64)

// ---------------- scratch (static device memory) ---------------------------
__device__ __align__(16) float g_users[(size_t)BATCH * N_ITEMS];           // 4 MB fp32
__device__ __align__(16) __nv_bfloat16 g_users_bf[(size_t)BATCH * N_ITEMS];// 2 MB
__device__ __align__(16) unsigned long long g_pk[(size_t)BATCH * NBLK * PK]; // 3.2 MB
__device__ float g_inv_na[U_ROWS];
__device__ float g_inv_nu[BATCH];
__device__ int   g_cand_idx[BATCH * CAND];
__device__ int   g_k;

// ---------------- helpers ---------------------------------------------------
__device__ __forceinline__ uint32_t smem_u32(const void* p) {
    uint32_t a;
    asm("{ .reg .u64 t; cvta.to.shared.u64 t, %1; cvt.u32.u64 %0, t; }" : "=r"(a) : "l"(p));
    return a;
}
#define CP_ASYNC16(dst, src) \
    asm volatile("cp.async.cg.shared.global [%0], [%1], 16;" :: "r"(dst), "l"(src))
#define CP_COMMIT() asm volatile("cp.async.commit_group;" ::: "memory")
#define CP_WAIT(n)  asm volatile("cp.async.wait_group %0;" :: "n"(n) : "memory")

__device__ __forceinline__ float neg_inf() { return __int_as_float(0xFF800000); }
__device__ __forceinline__ unsigned bf16u(float x) {
    return (unsigned)__bfloat16_as_ushort(__float2bfloat16_rn(x));
}
__device__ __forceinline__ uint32_t pack_bf2(float a, float b) {
    uint32_t r;
    asm("cvt.rn.bf16x2.f32 %0, %2, %1;" : "=r"(r) : "f"(a), "f"(b));
    return r;
}
// swizzled chunk byte offset within a 64B-row tile
__device__ __forceinline__ uint32_t swz64(int row, int c) {
    return (uint32_t)(row * 64 + 16 * (c ^ ((row >> 1) & 3)));
}
// order-preserving composite key: (value desc, index asc); key > 0 for v >= 0
__device__ __forceinline__ unsigned long long okey(float v, int idx) {
    unsigned kb = __float_as_uint(v);
    kb ^= (kb >> 31) ? 0xFFFFFFFFu : 0x80000000u;
    return ((unsigned long long)kb << 32) |
           (unsigned long long)(0xFFFFFFFFu - (unsigned)idx);
}
__device__ __forceinline__ int okey_idx(unsigned long long k) {
    return (int)(0xFFFFFFFFu - (unsigned)(k & 0xFFFFFFFFull));
}

// ---------------- kernel 1: gather users + norms + mode/k detection ---------
__global__ void gather_users_kernel(const float* __restrict__ F, const void* ids,
                                    const int* kptr, int has_k) {
    const int b = blockIdx.x;
    const int tid = threadIdx.x;   // 512 threads

    __shared__ int s_is64;
    if (tid == 0) {
        const unsigned* w = (const unsigned*)ids;
        bool is64 = true;
        for (int i = 0; i < 16; i++)
            if (w[2 * i + 1] != 0u) { is64 = false; break; }
        s_is64 = is64 ? 1 : 0;
        if (b == 0) {
            int kk = 10;
            if (has_k) {
                int vi = kptr[0];
                if (vi >= 1 && vi <= MAXK) kk = vi;
                else {
                    float vf = __int_as_float(vi);
                    if (vf >= 1.f && vf <= (float)MAXK) kk = (int)vf;
                }
            }
            g_k = kk;
        }
    }
    __syncthreads();

    long long uid;
    if (s_is64) uid = ((const long long*)ids)[b];
    else        uid = (long long)((const int*)ids)[b];
    const float4* src = (const float4*)(F + (size_t)uid * N_ITEMS);
    float4* dstf = (float4*)(g_users + (size_t)b * N_ITEMS);
    uint2* dstb = (uint2*)(g_users_bf + (size_t)b * N_ITEMS);
    float s = 0.f;
    for (int v = tid; v < N_ITEMS / 4; v += 512) {
        float4 x = src[v];
        dstf[v] = x;
        uint2 o;
        o.x = bf16u(x.x) | (bf16u(x.y) << 16);
        o.y = bf16u(x.z) | (bf16u(x.w) << 16);
        dstb[v] = o;
        s += x.x * x.x + x.y * x.y + x.z * x.z + x.w * x.w;
    }
    for (int off = 16; off > 0; off >>= 1)
        s += __shfl_down_sync(0xFFFFFFFFu, s, off);
    __shared__ float ws[16];
    if ((tid & 31) == 0) ws[tid >> 5] = s;
    __syncthreads();
    if (tid == 0) {
        float t = 0.f;
        for (int i = 0; i < 16; i++) t += ws[i];
        g_inv_nu[b] = 1.0f / fmaxf(t, 1e-8f);
    }
}

// ---------------- kernel 2: bf16 mma GEMM + fused per-CTA top-PK ------------
__global__ __launch_bounds__(NTHREADS, 1)
void gemm_sim_kernel(const float* __restrict__ F) {
    extern __shared__ __align__(1024) char smem[];
    const uint32_t sbase = smem_u32(smem);
    const int tid = threadIdx.x;
    const int lane = tid & 31;
    const int wid = tid >> 5;
    const int m0 = blockIdx.x * 128;
    const int mw = wid & 1;       // warp M index
    const int nw = wid >> 1;      // warp N index (0..7), warp tile 64x32

    float* invna_s = (float*)(smem + OFF_INVNA);
    float* invnu_s = (float*)(smem + OFF_INVNU);
    if (tid < 256) invnu_s[tid] = g_inv_nu[tid];

    // ---- A producer (fp32 LDG -> cvt -> STS): thread owns (row, 16B chunk) ----
    const int arow = tid >> 2;           // 0..127
    const int ach = tid & 3;             // bf16 16B chunk == fp32 32B chunk
    int gm = m0 + arow; if (gm > U_ROWS - 1) gm = U_ROWS - 1;
    const char* asrc = (const char*)F + (size_t)gm * (N_ITEMS * 4) + ach * 32;
    const uint32_t asts = swz64(arow, ach);

    // ---- B producer (cp.async from bf16 users): rows arow, arow+128 ----
    const char* bsrc0 = (const char*)g_users_bf + (size_t)arow * (N_ITEMS * 2) + ach * 16;
    const char* bsrc1 = bsrc0 + (size_t)128 * (N_ITEMS * 2);
    const uint32_t bst0 = 8192 + swz64(arow, ach);
    const uint32_t bst1 = 8192 + swz64(arow + 128, ach);

    // ---- A fragment (ldmatrix) per-lane constants ----
    const int ahalf = lane >> 4;
    uint32_t a_base[4];
    int a_sw[4];
#pragma unroll
    for (int f = 0; f < 4; f++) {
        int r = mw * 64 + f * 16 + (lane & 15);
        a_base[f] = (uint32_t)(r * 64);
        a_sw[f] = (r >> 1) & 3;
    }
    // ---- B fragment (ldmatrix x4 over 16n x 16k) per-lane constants ----
    const int grp = lane >> 3;
    const int cbit = grp & 1;
    uint32_t b_base[2];
    int b_sw[2];
#pragma unroll
    for (int gp = 0; gp < 2; gp++) {
        int n = nw * 32 + gp * 16 + ((grp & 2) << 2) + (lane & 7);
        b_base[gp] = (uint32_t)(8192 + n * 64);
        b_sw[gp] = (n >> 1) & 3;
    }

    float c[4][4][4];
#pragma unroll
    for (int f = 0; f < 4; f++)
#pragma unroll
        for (int g = 0; g < 4; g++)
#pragma unroll
            for (int i = 0; i < 4; i++) c[f][g][i] = 0.f;

    float ns = 0.f;
    float4 av0, av1;

    auto ldgA = [&](int kt) {
        const char* p = asrc + (size_t)kt * (BK * 4);
        av0 = *(const float4*)p;
        av1 = *(const float4*)(p + 16);
    };
    auto stsA = [&](uint32_t stagebase) {
        ns += av0.x * av0.x + av0.y * av0.y + av0.z * av0.z + av0.w * av0.w;
        ns += av1.x * av1.x + av1.y * av1.y + av1.z * av1.z + av1.w * av1.w;
        uint32_t p0 = pack_bf2(av0.x, av0.y);
        uint32_t p1 = pack_bf2(av0.z, av0.w);
        uint32_t p2 = pack_bf2(av1.x, av1.y);
        uint32_t p3 = pack_bf2(av1.z, av1.w);
        asm volatile("st.shared.v4.b32 [%0], {%1,%2,%3,%4};"
                     :: "r"(stagebase + asts), "r"(p0), "r"(p1), "r"(p2), "r"(p3)
                     : "memory");
    };
    auto issueB = [&](int kt) {
        uint32_t stb = sbase + (kt % 3) * STAGE_BYTES;
        CP_ASYNC16(stb + bst0, bsrc0 + (size_t)kt * (BK * 2));
        CP_ASYNC16(stb + bst1, bsrc1 + (size_t)kt * (BK * 2));
    };

    // ---- prologue ----
    issueB(0); CP_COMMIT();
    issueB(1); CP_COMMIT();
    ldgA(0);
    stsA(sbase);
    ldgA(1);

    // ---- mainloop ----
    for (int kt = 0; kt < KITERS; ++kt) {
        CP_WAIT(1);
        __syncthreads();
        if (kt + 2 < KITERS) issueB(kt + 2);
        CP_COMMIT();
        if (kt + 1 < KITERS) stsA(sbase + ((kt + 1) % 3) * STAGE_BYTES);
        if (kt + 2 < KITERS) ldgA(kt + 2);

        const uint32_t stb = sbase + (kt % 3) * STAGE_BYTES;
#pragma unroll
        for (int s = 0; s < 2; ++s) {
            uint32_t af[4][4];
#pragma unroll
            for (int f = 0; f < 4; ++f) {
                uint32_t addr = stb + a_base[f] +
                                (uint32_t)(16 * ((2 * s + ahalf) ^ a_sw[f]));
                asm volatile("ldmatrix.sync.aligned.m8n8.x4.shared.b16 {%0,%1,%2,%3}, [%4];"
                             : "=r"(af[f][0]), "=r"(af[f][1]), "=r"(af[f][2]), "=r"(af[f][3])
                             : "r"(addr));
            }
#pragma unroll
            for (int gp = 0; gp < 2; ++gp) {
                uint32_t bf0, bf1, bf2, bf3;
                uint32_t addr = stb + b_base[gp] +
                                (uint32_t)(16 * ((2 * s + cbit) ^ b_sw[gp]));
                asm volatile("ldmatrix.sync.aligned.m8n8.x4.shared.b16 {%0,%1,%2,%3}, [%4];"
                             : "=r"(bf0), "=r"(bf1), "=r"(bf2), "=r"(bf3)
                             : "r"(addr));
#pragma unroll
                for (int f = 0; f < 4; ++f) {
                    asm volatile(
                        "mma.sync.aligned.m16n8k16.row.col.f32.bf16.bf16.f32 "
                        "{%0,%1,%2,%3}, {%4,%5,%6,%7}, {%8,%9}, {%0,%1,%2,%3};"
                        : "+f"(c[f][2 * gp][0]), "+f"(c[f][2 * gp][1]),
                          "+f"(c[f][2 * gp][2]), "+f"(c[f][2 * gp][3])
                        : "r"(af[f][0]), "r"(af[f][1]), "r"(af[f][2]), "r"(af[f][3]),
                          "r"(bf0), "r"(bf1));
                    asm volatile(
                        "mma.sync.aligned.m16n8k16.row.col.f32.bf16.bf16.f32 "
                        "{%0,%1,%2,%3}, {%4,%5,%6,%7}, {%8,%9}, {%0,%1,%2,%3};"
                        : "+f"(c[f][2 * gp + 1][0]), "+f"(c[f][2 * gp + 1][1]),
                          "+f"(c[f][2 * gp + 1][2]), "+f"(c[f][2 * gp + 1][3])
                        : "r"(af[f][0]), "r"(af[f][1]), "r"(af[f][2]), "r"(af[f][3]),
                          "r"(bf2), "r"(bf3));
                }
            }
        }
    }

    CP_WAIT(0);
    __syncthreads();

    // ---- exact row norms: reduce over the 4 threads sharing a row ----
    {
        float v = ns;
        v += __shfl_xor_sync(0xFFFFFFFFu, v, 1);
        v += __shfl_xor_sync(0xFFFFFFFFu, v, 2);
        if ((tid & 3) == 0) {
            float inv = 1.0f / fmaxf(v, 1e-8f);
            invna_s[arow] = inv;
            if (m0 + arow < U_ROWS) g_inv_na[m0 + arow] = inv;
        }
    }
    __syncthreads();

    // ---- stage scaled sims to Csm[128][257] (reuses stage smem) ----
    float* Csm = (float*)smem;
#pragma unroll
    for (int f = 0; f < 4; ++f) {
        int r0 = mw * 64 + f * 16 + (lane >> 2);
        float na0 = invna_s[r0], na8 = invna_s[r0 + 8];
#pragma unroll
        for (int g = 0; g < 4; ++g) {
            int col = nw * 32 + g * 8 + 2 * (lane & 3);
            float nu0 = invnu_s[col], nu1 = invnu_s[col + 1];
            Csm[r0 * 257 + col]           = c[f][g][0] * na0 * nu0;
            Csm[r0 * 257 + col + 1]       = c[f][g][1] * na0 * nu1;
            Csm[(r0 + 8) * 257 + col]     = c[f][g][2] * na8 * nu0;
            Csm[(r0 + 8) * 257 + col + 1] = c[f][g][3] * na8 * nu1;
        }
    }
    __syncthreads();

    // ---- per-(column, half) top-PK over 64 rows, all 512 threads ----
    unsigned long long* pkb = (unsigned long long*)(smem + OFF_PKBUF);
    {
        const int col = tid & 255;
        const int half = tid >> 8;
        unsigned long long kk[PK];
#pragma unroll
        for (int j = 0; j < PK; j++) kk[j] = 0ull;

        int rbeg = half * 64;
        int rend = rbeg + 64;
        int rmax = U_ROWS - m0;
        if (rend > rmax) rend = rmax;
        for (int r = rbeg; r < rend; ++r) {
            unsigned long long key = okey(Csm[r * 257 + col], m0 + r);
            if (key > kk[PK - 1]) {
                unsigned long long ck = key;
#pragma unroll
                for (int j = 0; j < PK; j++) {
                    if (ck > kk[j]) {
                        unsigned long long t = kk[j];
                        kk[j] = ck; ck = t;
                    }
                }
            }
        }
        unsigned long long* dst = pkb + (size_t)tid * PK;
#pragma unroll
        for (int j = 0; j < PK; j++) dst[j] = kk[j];
    }
    __syncthreads();

    // ---- merge the two sorted halves per column -> g_pk ----
    if (tid < 256) {
        const unsigned long long* a = pkb + (size_t)tid * PK;
        const unsigned long long* bb = pkb + (size_t)(tid + 256) * PK;
        unsigned long long* dst = g_pk + ((size_t)tid * NBLK + blockIdx.x) * PK;
        int p = 0, q = 0;
#pragma unroll
        for (int r = 0; r < PK; ++r) {
            unsigned long long ka = a[p], kb = bb[q];
            bool ta = ka >= kb;
            dst[r] = ta ? ka : kb;
            p += ta; q += !ta;
        }
    }
}

// ---------------- kernel 3: select top-CAND candidates from partials --------
#define SLOCK 8
__global__ void select_cand_kernel() {
    const int b = blockIdx.x;
    const int tid = threadIdx.x;     // 128 threads
    const int lane = tid & 31;
    const int wid = tid >> 5;

    const unsigned long long* src = g_pk + (size_t)b * NBLK * PK;  // 1564 keys

    unsigned long long kk[SLOCK];
#pragma unroll
    for (int j = 0; j < SLOCK; j++) kk[j] = 0ull;

    for (int i = tid; i < NBLK * PK; i += 128) {
        unsigned long long key = src[i];
        if (key > kk[SLOCK - 1]) {
            unsigned long long ck = key;
#pragma unroll
            for (int j = 0; j < SLOCK; j++) {
                if (ck > kk[j]) {
                    unsigned long long t = kk[j];
                    kk[j] = ck; ck = t;
                }
            }
        }
    }

    __shared__ unsigned long long wbest[4];
    __shared__ int wtid[4];
    __shared__ int swin;

    for (int r = 0; r < CAND; ++r) {
        unsigned long long best = kk[0];
        int bt = tid;
#pragma unroll
        for (int o = 16; o > 0; o >>= 1) {
            unsigned long long ob = __shfl_down_sync(0xFFFFFFFFu, best, o);
            int ot = __shfl_down_sync(0xFFFFFFFFu, bt, o);
            if (ob > best) { best = ob; bt = ot; }
        }
        if (lane == 0) { wbest[wid] = best; wtid[wid] = bt; }
        __syncthreads();
        if (tid == 0) {
            unsigned long long m = wbest[0]; int mt = wtid[0];
            for (int i = 1; i < 4; i++)
                if (wbest[i] > m) { m = wbest[i]; mt = wtid[i]; }
            swin = mt;
        }
        __syncthreads();
        if (tid == swin) {
            g_cand_idx[b * CAND + r] = okey_idx(kk[0]);
#pragma unroll
            for (int j = 0; j < SLOCK - 1; j++) kk[j] = kk[j + 1];
            kk[SLOCK - 1] = 0ull;
        }
        __syncthreads();
    }
}

// ---------------- kernel 4: exact fp32 rescore + top-k + ratings ------------
__global__ void rescore_ratings_kernel(const float* __restrict__ F,
                                       float* __restrict__ out) {
    const int b = blockIdx.x;
    const int tid = threadIdx.x;     // 512 threads = 16 warps
    const int lane = tid & 31;
    const int w = tid >> 5;

    __shared__ float ssim[CAND];
    __shared__ int   sidx[CAND];
    __shared__ float wgt[CAND];
    __shared__ int   nid[CAND];

    // ---- exact rescore: one warp per candidate (16 warps = CAND) ----
    {
        const float* ub = g_users + (size_t)b * N_ITEMS;
        const float inv_nu = g_inv_nu[b];
        int u = g_cand_idx[b * CAND + w];
        const float* fu = F + (size_t)u * N_ITEMS;
        float acc = 0.f;
#pragma unroll 4
        for (int k = lane; k < N_ITEMS / 4; k += 32) {
            float4 x = ((const float4*)ub)[k];
            float4 y = ((const float4*)fu)[k];
            acc += x.x * y.x + x.y * y.y + x.z * y.z + x.w * y.w;
        }
        for (int o = 16; o > 0; o >>= 1)
            acc += __shfl_down_sync(0xFFFFFFFFu, acc, o);
        if (lane == 0) {
            ssim[w] = acc * g_inv_na[u] * inv_nu;
            sidx[w] = u;
        }
    }
    __syncthreads();

    // ---- exact top-k with jax tie-break + weights (thread 0; k small) ----
    if (tid == 0) {
        int k = g_k < CAND ? g_k : CAND;
        bool used[CAND];
        for (int i = 0; i < CAND; i++) used[i] = false;
        float s = 0.f;
        for (int r = 0; r < k; r++) {
            int bi = -1;
            float bv = neg_inf();
            int bidx = 0x7FFFFFFF;
            for (int cc = 0; cc < CAND; cc++) {
                if (used[cc]) continue;
                float v = ssim[cc];
                if (v > bv || (v == bv && sidx[cc] < bidx)) {
                    bv = v; bidx = sidx[cc]; bi = cc;
                }
            }
            used[bi] = true;
            wgt[r] = bv;
            nid[r] = bidx;
            s += bv;
        }
        float inv = 1.0f / s;
        for (int r = 0; r < k; r++) wgt[r] *= inv;
    }
    __syncthreads();

    // ---- weighted neighbor gather: float4 chunks (1000 over 512 threads) ----
    {
        int k = g_k < CAND ? g_k : CAND;
        float4* out4 = (float4*)(out + (size_t)b * N_ITEMS);
        for (int i = tid; i < N_ITEMS / 4; i += 512) {
            float4 acc = make_float4(0.f, 0.f, 0.f, 0.f);
            for (int j = 0; j < k; j++) {
                float wj = wgt[j];
                float4 y = ((const float4*)(F + (size_t)nid[j] * N_ITEMS))[i];
                acc.x += wj * y.x;
                acc.y += wj * y.y;
                acc.z += wj * y.z;
                acc.w += wj * y.w;
            }
            out4[i] = acc;
        }
    }
}

// ---------------- launch ----------------------------------------------------
extern "C" void kernel_launch(void* const* d_in, const int* in_sizes, int n_in,
                              void* d_out, int out_size) {
    const float* F = (const float*)d_in[0];
    const void* ids = d_in[1];
    const int* kptr = (n_in > 2) ? (const int*)d_in[2] : nullptr;

    cudaFuncSetAttribute(gemm_sim_kernel,
                         cudaFuncAttributeMaxDynamicSharedMemorySize, SMEM_TOTAL);

    gather_users_kernel<<<BATCH, 512>>>(F, ids, kptr, kptr != nullptr ? 1 : 0);

    gemm_sim_kernel<<<NBLK, NTHREADS, SMEM_TOTAL>>>(F);

    select_cand_kernel<<<BATCH, 128>>>();
    rescore_ratings_kernel<<<BATCH, 512>>>(F, (float*)d_out);
}